// round 3
// baseline (speedup 1.0000x reference)
#include <cuda_runtime.h>

#define NPTS   2000000
#define NCOMP  48
#define G      300
#define TBLF   (G * NCOMP)                 // 14400 floats per table (dense [G][48])
#define TBL3   (3 * TBLF)                  // 43200 floats
#define BLK    1024
#define WARPS  (BLK / 32)                  // 32
#define TILE   8                           // points per warp-tile
#define SSTR   9                           // staging row stride (floats)
#define STAGEW (NCOMP * SSTR)              // 432 floats per warp
#define SMEM_BYTES ((TBL3 + WARPS * STAGEW) * 4)   // 228096 B (<= 227 KB)
#define NBLOCKS 152
#define TILES  (NPTS / TILE)               // 250000 (exact)

__device__ float g_pT[TBL3];

// Transpose each param [C=48, G=300] -> dense [G][48].
__global__ void cp_prep(const float* __restrict__ p0,
                        const float* __restrict__ p1,
                        const float* __restrict__ p2) {
    int idx = blockIdx.x * blockDim.x + threadIdx.x;
    if (idx >= TBL3) return;
    int t   = idx / TBLF;
    int rem = idx - t * TBLF;
    int g   = rem / NCOMP;
    int c   = rem - g * NCOMP;
    const float* p = (t == 0) ? p0 : ((t == 1) ? p1 : p2);
    g_pT[idx] = p[c * G + g];
}

// Conflict-free per-dim fetch + lerp. 8 lanes (j=0..7) serve one point.
// v  = comps 4j..4j+3; ve = comps 32+4(j&3).. (valid on jlow lanes).
__device__ __forceinline__ void interp_dim(const float4* __restrict__ T4,
                                           int base4_0, int base4_1,
                                           float w, int j, bool jlow,
                                           float4& v, float4& ve) {
    float4 a0 = T4[base4_0 + j];                        // tap0 chunks 0..7
    float4 a1 = T4[base4_1 + j];                        // tap1 chunks 0..7
    int eidx  = jlow ? (base4_0 + 8 + j) : (base4_1 + 4 + j);
    float4 ae = T4[eidx];                               // mixed extras (conflict-free)

    v.x = fmaf(w, a1.x - a0.x, a0.x);
    v.y = fmaf(w, a1.y - a0.y, a0.y);
    v.z = fmaf(w, a1.z - a0.z, a0.z);
    v.w = fmaf(w, a1.w - a0.w, a0.w);

    float4 ao;
    ao.x = __shfl_xor_sync(0xffffffffu, ae.x, 4);
    ao.y = __shfl_xor_sync(0xffffffffu, ae.y, 4);
    ao.z = __shfl_xor_sync(0xffffffffu, ae.z, 4);
    ao.w = __shfl_xor_sync(0xffffffffu, ae.w, 4);

    // jlow:  ae=t0e, ao=t1e -> ve = ae + w*(ao-ae)
    // jhigh: ae=t1e, ao=t0e -> ve = ae + (1-w)*(ao-ae)
    float wl = jlow ? w : (1.0f - w);
    ve.x = fmaf(wl, ao.x - ae.x, ae.x);
    ve.y = fmaf(wl, ao.y - ae.y, ae.y);
    ve.z = fmaf(wl, ao.z - ae.z, ae.z);
    ve.w = fmaf(wl, ao.w - ae.w, ae.w);
}

__global__ __launch_bounds__(BLK, 1) void cp_eval(const float* __restrict__ xyz,
                                                  float* __restrict__ out) {
    extern __shared__ float sh[];
    {
        const float4* src = (const float4*)g_pT;
        float4* dst = (float4*)sh;
        for (int i = threadIdx.x; i < TBL3 / 4; i += BLK) dst[i] = src[i];
    }
    __syncthreads();

    const int lane = threadIdx.x & 31;
    const int warp = threadIdx.x >> 5;
    const int j    = lane & 7;          // chunk lane within point group
    const int pg   = lane >> 3;         // point group 0..3
    const bool jlow = (j < 4);

    const float4* T4 = (const float4*)sh;
    float* stg = sh + TBL3 + warp * STAGEW;

    const int gw = blockIdx.x * WARPS + warp;
    const int c4 = lane >> 3;           // readback: comp sub-index 0..3
    const int pp = lane & 7;            // readback: point within tile

    for (int tile = gw; tile < TILES; tile += NBLOCKS * WARPS) {
        const int n0 = tile * TILE;

        #pragma unroll
        for (int s = 0; s < 2; s++) {
            const int p8 = s * 4 + pg;
            const int n  = n0 + p8;

            float x = __ldg(xyz + 3 * n + 0);
            float y = __ldg(xyz + 3 * n + 1);
            float z = __ldg(xyz + 3 * n + 2);

            float px = (x + 1.0f) * 0.5f * (float)(G - 1);
            float py = (y + 1.0f) * 0.5f * (float)(G - 1);
            float pz = (z + 1.0f) * 0.5f * (float)(G - 1);

            int i0x = min(max((int)floorf(px), 0), G - 1);
            int i0y = min(max((int)floorf(py), 0), G - 1);
            int i0z = min(max((int)floorf(pz), 0), G - 1);
            int i1x = min(i0x + 1, G - 1);
            int i1y = min(i0y + 1, G - 1);
            int i1z = min(i0z + 1, G - 1);

            float wx = px - (float)i0x;
            float wy = py - (float)i0y;
            float wz = pz - (float)i0z;

            int bx0 = 0 * (TBLF / 4) + 12 * i0x, bx1 = 0 * (TBLF / 4) + 12 * i1x;
            int by0 = 1 * (TBLF / 4) + 12 * i0y, by1 = 1 * (TBLF / 4) + 12 * i1y;
            int bz0 = 2 * (TBLF / 4) + 12 * i0z, bz1 = 2 * (TBLF / 4) + 12 * i1z;

            float4 vx, vxe, vy, vye, vz, vze;
            interp_dim(T4, bx0, bx1, wx, j, jlow, vx, vxe);
            interp_dim(T4, by0, by1, wy, j, jlow, vy, vye);
            interp_dim(T4, bz0, bz1, wz, j, jlow, vz, vze);

            float4 f, fe;
            f.x = vx.x * vy.x * vz.x;   f.y = vx.y * vy.y * vz.y;
            f.z = vx.z * vy.z * vz.z;   f.w = vx.w * vy.w * vz.w;
            fe.x = vxe.x * vye.x * vze.x;  fe.y = vxe.y * vye.y * vze.y;
            fe.z = vxe.z * vye.z * vze.z;  fe.w = vxe.w * vye.w * vze.w;

            // Stage main chunks: banks (4j + 9i + p8) % 32 — all 32 distinct per instr.
            stg[(4 * j + 0) * SSTR + p8] = f.x;
            stg[(4 * j + 1) * SSTR + p8] = f.y;
            stg[(4 * j + 2) * SSTR + p8] = f.z;
            stg[(4 * j + 3) * SSTR + p8] = f.w;
            if (jlow) {                 // extras: comps 32+4j..35+4j
                stg[(32 + 4 * j + 0) * SSTR + p8] = fe.x;
                stg[(32 + 4 * j + 1) * SSTR + p8] = fe.y;
                stg[(32 + 4 * j + 2) * SSTR + p8] = fe.z;
                stg[(32 + 4 * j + 3) * SSTR + p8] = fe.w;
            }
        }
        __syncwarp();

        // Coalesced writeback: 4 comp-rows x 8 points per instr (32B runs).
        #pragma unroll
        for (int t = 0; t < 12; t++) {
            int c = t * 4 + c4;
            out[c * NPTS + n0 + pp] = stg[c * SSTR + pp];
        }
        __syncwarp();   // staging reused next tile
    }
}

extern "C" void kernel_launch(void* const* d_in, const int* in_sizes, int n_in,
                              void* d_out, int out_size) {
    const float* xyz = (const float*)d_in[0];
    const float* p0  = (const float*)d_in[1];
    const float* p1  = (const float*)d_in[2];
    const float* p2  = (const float*)d_in[3];
    float* out = (float*)d_out;

    cp_prep<<<(TBL3 + 255) / 256, 256>>>(p0, p1, p2);

    static bool attr_set = false;
    if (!attr_set) {
        cudaFuncSetAttribute(cp_eval, cudaFuncAttributeMaxDynamicSharedMemorySize, SMEM_BYTES);
        attr_set = true;
    }
    cp_eval<<<NBLOCKS, BLK, SMEM_BYTES>>>(xyz, out);
}

// round 4
// speedup vs baseline: 1.6972x; 1.6972x over previous
#include <cuda_runtime.h>

#define NPTS    2000000
#define NCOMP   48
#define G       300
#define BLK     512
#define WARPS   (BLK / 32)               // 16
#define NBLOCKS 152
#define TILES   (NPTS / 32)              // 62500 (exact)

#define TAB_F4  (G * 8)                  // 2400 float4 per table (rows of 8 f4 = 32 floats)
#define TAB3_F4 (3 * TAB_F4)             // 7200 float4 = 115200 B
#define STG_ROW 33                       // staging row stride in float4 (8 rows per warp)
#define STG_W   (8 * STG_ROW)            // 264 f4 per warp
#define SMEM_BYTES ((TAB3_F4 + WARPS * STG_W) * 16)   // 182784 B

// Split tables, rows padded to 32 floats (128B => every row starts at bank group 0).
// A: comps 0..31.  B: comps 32..47 in chunks 0..3, chunks 4..7 zero.
__device__ float g_tA[3 * G * 32];
__device__ float g_tB[3 * G * 32];

__global__ void cp_prep(const float* __restrict__ p0,
                        const float* __restrict__ p1,
                        const float* __restrict__ p2) {
    int idx = blockIdx.x * blockDim.x + threadIdx.x;   // over 3*300*32
    if (idx >= 3 * G * 32) return;
    int d   = idx / (G * 32);
    int rem = idx - d * (G * 32);
    int g   = rem >> 5;
    int c   = rem & 31;
    const float* p = (d == 0) ? p0 : ((d == 1) ? p1 : p2);
    g_tA[idx] = p[c * G + g];
    g_tB[idx] = (c < 16) ? p[(32 + c) * G + g] : 0.0f;
}

// One lane = one point. At step k, lane loads chunk c = k ^ (lane&7) of all 6 rows:
// row base group is always 0 (128B rows), so phase bank groups = {c} = bijection
// => conflict-free, no shuffles. Results realigned via XOR-swizzled staging so the
// final STG is one full-coalesced component row per instruction.
template <int NREAL>
__global__ __launch_bounds__(BLK, 1) void cp_eval(const float* __restrict__ xyz,
                                                  float* __restrict__ out,
                                                  const float4* __restrict__ gtab,
                                                  int compBase) {
    extern __shared__ float4 sh4[];
    for (int i = threadIdx.x; i < TAB3_F4; i += BLK) sh4[i] = gtab[i];
    __syncthreads();

    const int lane = threadIdx.x & 31;
    const int warp = threadIdx.x >> 5;
    const int l7   = lane & 7;
    const int lhi  = lane & 24;
    float4* stg = sh4 + TAB3_F4 + warp * STG_W;

    const int gw = blockIdx.x * WARPS + warp;

    for (int tile = gw; tile < TILES; tile += NBLOCKS * WARPS) {
        const int n = tile * 32 + lane;

        float x = xyz[3 * n + 0];
        float y = xyz[3 * n + 1];
        float z = xyz[3 * n + 2];

        float px = (x + 1.0f) * 0.5f * (float)(G - 1);
        float py = (y + 1.0f) * 0.5f * (float)(G - 1);
        float pz = (z + 1.0f) * 0.5f * (float)(G - 1);

        int i0x = min(max((int)floorf(px), 0), G - 1);
        int i0y = min(max((int)floorf(py), 0), G - 1);
        int i0z = min(max((int)floorf(pz), 0), G - 1);
        int i1x = min(i0x + 1, G - 1);
        int i1y = min(i0y + 1, G - 1);
        int i1z = min(i0z + 1, G - 1);

        float wx = px - (float)i0x;
        float wy = py - (float)i0y;
        float wz = pz - (float)i0z;

        const float4* bx0 = sh4 + 0 * TAB_F4 + 8 * i0x;
        const float4* bx1 = sh4 + 0 * TAB_F4 + 8 * i1x;
        const float4* by0 = sh4 + 1 * TAB_F4 + 8 * i0y;
        const float4* by1 = sh4 + 1 * TAB_F4 + 8 * i1y;
        const float4* bz0 = sh4 + 2 * TAB_F4 + 8 * i0z;
        const float4* bz1 = sh4 + 2 * TAB_F4 + 8 * i1z;

        #pragma unroll
        for (int k = 0; k < 8; k++) {
            int c = k ^ l7;
            if (c < NREAL) {
                float4 a0 = bx0[c], a1 = bx1[c];
                float4 b0 = by0[c], b1 = by1[c];
                float4 d0 = bz0[c], d1 = bz1[c];

                float vx0 = fmaf(wx, a1.x - a0.x, a0.x);
                float vx1 = fmaf(wx, a1.y - a0.y, a0.y);
                float vx2 = fmaf(wx, a1.z - a0.z, a0.z);
                float vx3 = fmaf(wx, a1.w - a0.w, a0.w);

                float vy0 = fmaf(wy, b1.x - b0.x, b0.x);
                float vy1 = fmaf(wy, b1.y - b0.y, b0.y);
                float vy2 = fmaf(wy, b1.z - b0.z, b0.z);
                float vy3 = fmaf(wy, b1.w - b0.w, b0.w);

                float vz0 = fmaf(wz, d1.x - d0.x, d0.x);
                float vz1 = fmaf(wz, d1.y - d0.y, d0.y);
                float vz2 = fmaf(wz, d1.z - d0.z, d0.z);
                float vz3 = fmaf(wz, d1.w - d0.w, d0.w);

                float4 f;
                f.x = vx0 * vy0 * vz0;
                f.y = vx1 * vy1 * vz1;
                f.z = vx2 * vy2 * vz2;
                f.w = vx3 * vy3 * vz3;

                // XOR-swizzled: phase bank group = (c + k) mod 8, conflict-free.
                stg[c * STG_ROW + ((lane ^ c) & 7) + lhi] = f;
            }
        }
        __syncwarp();

        // Readback chunk-major: all lanes same chunk c -> coalesced 128B STG rows.
        #pragma unroll
        for (int c = 0; c < NREAL; c++) {
            float4 v = stg[c * STG_ROW + ((lane ^ c) & 7) + lhi];
            int row = (compBase + 4 * c) * NPTS + tile * 32 + lane;
            out[row           ] = v.x;
            out[row +     NPTS] = v.y;
            out[row + 2 * NPTS] = v.z;
            out[row + 3 * NPTS] = v.w;
        }
        __syncwarp();   // staging reused next tile
    }
}

extern "C" void kernel_launch(void* const* d_in, const int* in_sizes, int n_in,
                              void* d_out, int out_size) {
    const float* xyz = (const float*)d_in[0];
    const float* p0  = (const float*)d_in[1];
    const float* p1  = (const float*)d_in[2];
    const float* p2  = (const float*)d_in[3];
    float* out = (float*)d_out;

    cp_prep<<<(3 * G * 32 + 255) / 256, 256>>>(p0, p1, p2);

    static bool attr_set = false;
    if (!attr_set) {
        cudaFuncSetAttribute(cp_eval<8>, cudaFuncAttributeMaxDynamicSharedMemorySize, SMEM_BYTES);
        cudaFuncSetAttribute(cp_eval<4>, cudaFuncAttributeMaxDynamicSharedMemorySize, SMEM_BYTES);
        attr_set = true;
    }

    float4* tA; float4* tB;
    cudaGetSymbolAddress((void**)&tA, g_tA);
    cudaGetSymbolAddress((void**)&tB, g_tB);

    cp_eval<8><<<NBLOCKS, BLK, SMEM_BYTES>>>(xyz, out, tA, 0);   // comps 0..31
    cp_eval<4><<<NBLOCKS, BLK, SMEM_BYTES>>>(xyz, out, tB, 32);  // comps 32..47
}

// round 5
// speedup vs baseline: 1.9167x; 1.1294x over previous
#include <cuda_runtime.h>

#define NPTS    2000000
#define NCOMP   48
#define G       300
#define BLK     512
#define WARPS   (BLK / 32)               // 16
#define NBLOCKS 152
#define TILES   (NPTS / 32)              // 62500 (exact)

#define TAB_F4  (G * 8)                  // 2400 float4 per table (rows of 8 f4 = 32 floats)
#define TAB3_F4 (3 * TAB_F4)             // 7200 float4 = 115200 B
#define STG_ROW 33                       // staging row stride in float4 (8 rows per warp)
#define STG_W   (8 * STG_ROW)            // 264 f4 per warp
#define SMEM_BYTES ((TAB3_F4 + WARPS * STG_W) * 16)   // 182784 B

// Split tables, rows padded to 32 floats (128B => every row starts at bank group 0).
// A: comps 0..31.  B: comps 32..47 in chunks 0..3, REPLICATED in chunks 4..7.
__device__ float g_tA[3 * G * 32];
__device__ float g_tB[3 * G * 32];

__global__ void cp_prep(const float* __restrict__ p0,
                        const float* __restrict__ p1,
                        const float* __restrict__ p2) {
    int idx = blockIdx.x * blockDim.x + threadIdx.x;   // over 3*300*32
    if (idx >= 3 * G * 32) return;
    int d   = idx / (G * 32);
    int rem = idx - d * (G * 32);
    int g   = rem >> 5;
    int c   = rem & 31;
    const float* p = (d == 0) ? p0 : ((d == 1) ? p1 : p2);
    g_tA[idx] = p[c * G + g];
    g_tB[idx] = p[(32 + (c & 15)) * G + g];            // replica in upper half
}

// Shared interp body: chunk c of all 6 rows -> f (product of 3 lerps).
__device__ __forceinline__ float4 lerp3(const float4* bx0, const float4* bx1,
                                        const float4* by0, const float4* by1,
                                        const float4* bz0, const float4* bz1,
                                        float wx, float wy, float wz, int c) {
    float4 a0 = bx0[c], a1 = bx1[c];
    float4 b0 = by0[c], b1 = by1[c];
    float4 d0 = bz0[c], d1 = bz1[c];

    float vx0 = fmaf(wx, a1.x - a0.x, a0.x);
    float vx1 = fmaf(wx, a1.y - a0.y, a0.y);
    float vx2 = fmaf(wx, a1.z - a0.z, a0.z);
    float vx3 = fmaf(wx, a1.w - a0.w, a0.w);

    float vy0 = fmaf(wy, b1.x - b0.x, b0.x);
    float vy1 = fmaf(wy, b1.y - b0.y, b0.y);
    float vy2 = fmaf(wy, b1.z - b0.z, b0.z);
    float vy3 = fmaf(wy, b1.w - b0.w, b0.w);

    float vz0 = fmaf(wz, d1.x - d0.x, d0.x);
    float vz1 = fmaf(wz, d1.y - d0.y, d0.y);
    float vz2 = fmaf(wz, d1.z - d0.z, d0.z);
    float vz3 = fmaf(wz, d1.w - d0.w, d0.w);

    float4 f;
    f.x = vx0 * vy0 * vz0;
    f.y = vx1 * vy1 * vz1;
    f.z = vx2 * vy2 * vz2;
    f.w = vx3 * vy3 * vz3;
    return f;
}

struct PtSetup {
    const float4 *bx0, *bx1, *by0, *by1, *bz0, *bz1;
    float wx, wy, wz;
};

__device__ __forceinline__ PtSetup setup_point(const float4* sh4,
                                               const float* __restrict__ xyz, int n) {
    float x = xyz[3 * n + 0];
    float y = xyz[3 * n + 1];
    float z = xyz[3 * n + 2];

    float px = (x + 1.0f) * 0.5f * (float)(G - 1);
    float py = (y + 1.0f) * 0.5f * (float)(G - 1);
    float pz = (z + 1.0f) * 0.5f * (float)(G - 1);

    int i0x = min(max((int)floorf(px), 0), G - 1);
    int i0y = min(max((int)floorf(py), 0), G - 1);
    int i0z = min(max((int)floorf(pz), 0), G - 1);
    int i1x = min(i0x + 1, G - 1);
    int i1y = min(i0y + 1, G - 1);
    int i1z = min(i0z + 1, G - 1);

    PtSetup s;
    s.wx = px - (float)i0x;
    s.wy = py - (float)i0y;
    s.wz = pz - (float)i0z;
    s.bx0 = sh4 + 0 * TAB_F4 + 8 * i0x;  s.bx1 = sh4 + 0 * TAB_F4 + 8 * i1x;
    s.by0 = sh4 + 1 * TAB_F4 + 8 * i0y;  s.by1 = sh4 + 1 * TAB_F4 + 8 * i1y;
    s.bz0 = sh4 + 2 * TAB_F4 + 8 * i0z;  s.bz1 = sh4 + 2 * TAB_F4 + 8 * i1z;
    return s;
}

// Pass A: comps 0..31, 8 full conflict-free steps (c = k ^ l7).
__global__ __launch_bounds__(BLK, 1) void cp_evalA(const float* __restrict__ xyz,
                                                   float* __restrict__ out,
                                                   const float4* __restrict__ gtab) {
    extern __shared__ float4 sh4[];
    for (int i = threadIdx.x; i < TAB3_F4; i += BLK) sh4[i] = gtab[i];
    __syncthreads();

    const int lane = threadIdx.x & 31;
    const int warp = threadIdx.x >> 5;
    const int l7   = lane & 7;
    const int lhi  = lane & 24;
    float4* stg = sh4 + TAB3_F4 + warp * STG_W;
    const int gw = blockIdx.x * WARPS + warp;

    for (int tile = gw; tile < TILES; tile += NBLOCKS * WARPS) {
        const int n = tile * 32 + lane;
        PtSetup s = setup_point(sh4, xyz, n);

        #pragma unroll
        for (int k = 0; k < 8; k++) {
            int c = k ^ l7;
            float4 f = lerp3(s.bx0, s.bx1, s.by0, s.by1, s.bz0, s.bz1,
                             s.wx, s.wy, s.wz, c);
            stg[c * STG_ROW + ((lane ^ c) & 7) + lhi] = f;   // group (c+k)%8: CF
        }
        __syncwarp();

        #pragma unroll
        for (int c = 0; c < 8; c++) {
            float4 v = stg[c * STG_ROW + ((lane ^ c) & 7) + lhi];
            int row = (4 * c) * NPTS + tile * 32 + lane;
            out[row           ] = v.x;
            out[row +     NPTS] = v.y;
            out[row + 2 * NPTS] = v.z;
            out[row + 3 * NPTS] = v.w;
        }
        __syncwarp();
    }
}

// Pass B: comps 32..47 via replicated table; 4 full conflict-free steps.
// Step k: c = k ^ l7 (all 8 groups), quad = c & 3, staged at (row c, col k).
// Readback quad q: lane j(=lane&7) reads row q|(j&4), col (q^j)&3 — CF.
__global__ __launch_bounds__(BLK, 1) void cp_evalB(const float* __restrict__ xyz,
                                                   float* __restrict__ out,
                                                   const float4* __restrict__ gtab) {
    extern __shared__ float4 sh4[];
    for (int i = threadIdx.x; i < TAB3_F4; i += BLK) sh4[i] = gtab[i];
    __syncthreads();

    const int lane = threadIdx.x & 31;
    const int warp = threadIdx.x >> 5;
    const int l7   = lane & 7;
    const int lhi  = lane & 24;
    float4* stg = sh4 + TAB3_F4 + warp * STG_W;
    const int gw = blockIdx.x * WARPS + warp;

    for (int tile = gw; tile < TILES; tile += NBLOCKS * WARPS) {
        const int n = tile * 32 + lane;
        PtSetup s = setup_point(sh4, xyz, n);

        #pragma unroll
        for (int k = 0; k < 4; k++) {
            int c = k ^ l7;
            float4 f = lerp3(s.bx0, s.bx1, s.by0, s.by1, s.bz0, s.bz1,
                             s.wx, s.wy, s.wz, c);
            stg[c * STG_ROW + k + lhi] = f;                  // col k, group (c+k)%8: CF
        }
        __syncwarp();

        #pragma unroll
        for (int q = 0; q < 4; q++) {
            int r   = q | (l7 & 4);
            int col = (q ^ l7) & 3;
            float4 v = stg[r * STG_ROW + col + lhi];
            int row = (32 + 4 * q) * NPTS + tile * 32 + lane;
            out[row           ] = v.x;
            out[row +     NPTS] = v.y;
            out[row + 2 * NPTS] = v.z;
            out[row + 3 * NPTS] = v.w;
        }
        __syncwarp();
    }
}

extern "C" void kernel_launch(void* const* d_in, const int* in_sizes, int n_in,
                              void* d_out, int out_size) {
    const float* xyz = (const float*)d_in[0];
    const float* p0  = (const float*)d_in[1];
    const float* p1  = (const float*)d_in[2];
    const float* p2  = (const float*)d_in[3];
    float* out = (float*)d_out;

    cp_prep<<<(3 * G * 32 + 255) / 256, 256>>>(p0, p1, p2);

    static bool attr_set = false;
    if (!attr_set) {
        cudaFuncSetAttribute(cp_evalA, cudaFuncAttributeMaxDynamicSharedMemorySize, SMEM_BYTES);
        cudaFuncSetAttribute(cp_evalB, cudaFuncAttributeMaxDynamicSharedMemorySize, SMEM_BYTES);
        attr_set = true;
    }

    float4* tA; float4* tB;
    cudaGetSymbolAddress((void**)&tA, g_tA);
    cudaGetSymbolAddress((void**)&tB, g_tB);

    cp_evalA<<<NBLOCKS, BLK, SMEM_BYTES>>>(xyz, out, tA);   // comps 0..31
    cp_evalB<<<NBLOCKS, BLK, SMEM_BYTES>>>(xyz, out, tB);   // comps 32..47
}

// round 6
// speedup vs baseline: 2.4101x; 1.2574x over previous
#include <cuda_runtime.h>
#include <cuda_fp16.h>

#define NPTS    2000000
#define G       300
#define BLK     512
#define WARPS   (BLK / 32)               // 16
#define NBLOCKS 152
#define TILES   (NPTS / 32)              // 62500 (exact)

#define ROW_F4  8                        // 8 float4 = 128 B/row = 64 halfs (48 used)
#define TAB_F4  (G * ROW_F4)             // 2400 f4 per table
#define TAB3_F4 (3 * TAB_F4)             // 7200 f4 = 115200 B
#define STG_ROW 33                       // staging row stride (float4)
#define STG_W   (12 * STG_ROW)           // 396 f4 per warp
#define SMEM_BYTES ((TAB3_F4 + WARPS * STG_W) * 16)   // 216576 B

// fp16 tables: [dim][g][64 halfs] — comps 0..47 real, 48..63 zero padding.
__device__ __half g_tH[3 * G * 64];

__global__ void cp_prep(const float* __restrict__ p0,
                        const float* __restrict__ p1,
                        const float* __restrict__ p2) {
    int idx = blockIdx.x * blockDim.x + threadIdx.x;   // over 3*300*64
    if (idx >= 3 * G * 64) return;
    int d   = idx / (G * 64);
    int rem = idx - d * (G * 64);
    int g   = rem >> 6;
    int c   = rem & 63;
    const float* p = (d == 0) ? p0 : ((d == 1) ? p1 : p2);
    float v = (c < 48) ? p[c * G + g] : 0.0f;
    g_tH[idx] = __float2half(v);
}

// Lerp 8 comps held as halfs inside two float4 raws; fp32 math.
__device__ __forceinline__ void lerp8(float4 r0, float4 r1, float w,
                                      float4& lo, float4& hi) {
    const __half2* A = reinterpret_cast<const __half2*>(&r0);
    const __half2* B = reinterpret_cast<const __half2*>(&r1);
    float2 a, b;
    a = __half22float2(A[0]); b = __half22float2(B[0]);
    lo.x = fmaf(w, b.x - a.x, a.x);  lo.y = fmaf(w, b.y - a.y, a.y);
    a = __half22float2(A[1]); b = __half22float2(B[1]);
    lo.z = fmaf(w, b.x - a.x, a.x);  lo.w = fmaf(w, b.y - a.y, a.y);
    a = __half22float2(A[2]); b = __half22float2(B[2]);
    hi.x = fmaf(w, b.x - a.x, a.x);  hi.y = fmaf(w, b.y - a.y, a.y);
    a = __half22float2(A[3]); b = __half22float2(B[3]);
    hi.z = fmaf(w, b.x - a.x, a.x);  hi.w = fmaf(w, b.y - a.y, a.y);
}

__global__ __launch_bounds__(BLK, 1) void cp_eval(const float* __restrict__ xyz,
                                                  float* __restrict__ out,
                                                  const float4* __restrict__ gtab) {
    extern __shared__ float4 sh4[];
    for (int i = threadIdx.x; i < TAB3_F4; i += BLK) sh4[i] = gtab[i];
    __syncthreads();

    const int lane = threadIdx.x & 31;
    const int warp = threadIdx.x >> 5;
    const int l7   = lane & 7;
    float4* stg = sh4 + TAB3_F4 + warp * STG_W;
    const int gw = blockIdx.x * WARPS + warp;

    for (int tile = gw; tile < TILES; tile += NBLOCKS * WARPS) {
        const int n = tile * 32 + lane;

        float x = xyz[3 * n + 0];
        float y = xyz[3 * n + 1];
        float z = xyz[3 * n + 2];

        float px = (x + 1.0f) * 0.5f * (float)(G - 1);
        float py = (y + 1.0f) * 0.5f * (float)(G - 1);
        float pz = (z + 1.0f) * 0.5f * (float)(G - 1);

        int i0x = min(max((int)floorf(px), 0), G - 1);
        int i0y = min(max((int)floorf(py), 0), G - 1);
        int i0z = min(max((int)floorf(pz), 0), G - 1);
        int i1x = min(i0x + 1, G - 1);
        int i1y = min(i0y + 1, G - 1);
        int i1z = min(i0z + 1, G - 1);

        float wx = px - (float)i0x;
        float wy = py - (float)i0y;
        float wz = pz - (float)i0z;

        const float4* bx0 = sh4 + 0 * TAB_F4 + ROW_F4 * i0x;
        const float4* bx1 = sh4 + 0 * TAB_F4 + ROW_F4 * i1x;
        const float4* by0 = sh4 + 1 * TAB_F4 + ROW_F4 * i0y;
        const float4* by1 = sh4 + 1 * TAB_F4 + ROW_F4 * i1y;
        const float4* bz0 = sh4 + 2 * TAB_F4 + ROW_F4 * i0z;
        const float4* bz1 = sh4 + 2 * TAB_F4 + ROW_F4 * i1z;

        // 8 XOR-rotation steps; chunks 6,7 don't exist -> predicated off.
        // Phase bank groups: loads = c (distinct per octet); staging stores
        // group (2c + lane) mod 8 -- bijection in lane for every k (verified).
        #pragma unroll
        for (int k = 0; k < 8; k++) {
            int c = k ^ l7;
            if (c < 6) {
                float4 xlo, xhi, ylo, yhi, zlo, zhi;
                lerp8(bx0[c], bx1[c], wx, xlo, xhi);
                lerp8(by0[c], by1[c], wy, ylo, yhi);
                lerp8(bz0[c], bz1[c], wz, zlo, zhi);

                float4 flo, fhi;
                flo.x = xlo.x * ylo.x * zlo.x;
                flo.y = xlo.y * ylo.y * zlo.y;
                flo.z = xlo.z * ylo.z * zlo.z;
                flo.w = xlo.w * ylo.w * zlo.w;
                fhi.x = xhi.x * yhi.x * zhi.x;
                fhi.y = xhi.y * yhi.y * zhi.y;
                fhi.z = xhi.z * yhi.z * zhi.z;
                fhi.w = xhi.w * yhi.w * zhi.w;

                stg[(2 * c + 0) * STG_ROW + lane] = flo;   // comps 8c..8c+3
                stg[(2 * c + 1) * STG_ROW + lane] = fhi;   // comps 8c+4..8c+7
            }
        }
        __syncwarp();

        // Readback own point's comps in static order -> coalesced STG.32.
        #pragma unroll
        for (int r = 0; r < 12; r++) {
            float4 v = stg[r * STG_ROW + lane];
            int row = (4 * r) * NPTS + tile * 32 + lane;
            out[row           ] = v.x;
            out[row +     NPTS] = v.y;
            out[row + 2 * NPTS] = v.z;
            out[row + 3 * NPTS] = v.w;
        }
        __syncwarp();   // staging reused next tile
    }
}

extern "C" void kernel_launch(void* const* d_in, const int* in_sizes, int n_in,
                              void* d_out, int out_size) {
    const float* xyz = (const float*)d_in[0];
    const float* p0  = (const float*)d_in[1];
    const float* p1  = (const float*)d_in[2];
    const float* p2  = (const float*)d_in[3];
    float* out = (float*)d_out;

    cp_prep<<<(3 * G * 64 + 255) / 256, 256>>>(p0, p1, p2);

    static bool attr_set = false;
    if (!attr_set) {
        cudaFuncSetAttribute(cp_eval, cudaFuncAttributeMaxDynamicSharedMemorySize, SMEM_BYTES);
        attr_set = true;
    }

    float4* tH;
    cudaGetSymbolAddress((void**)&tH, g_tH);

    cp_eval<<<NBLOCKS, BLK, SMEM_BYTES>>>(xyz, out, tH);
}

// round 7
// speedup vs baseline: 2.7961x; 1.1602x over previous
#include <cuda_runtime.h>
#include <cuda_fp16.h>

#define NPTS    2000000
#define G       300
#define BLK     512
#define WARPS   (BLK / 32)               // 16
#define NBLOCKS 152
#define TILES   (NPTS / 32)              // 62500 (exact)

#define ROW_F4  8                        // 8 float4 = 128 B/row = 64 halfs (48 used)
#define TAB_F4  (G * ROW_F4)             // 2400 f4 per table
#define TAB3_F4 (3 * TAB_F4)             // 7200 f4 = 115200 B
#define STG_ROW 34                       // staging row stride (float4): group=(2c+lane)&7, CF
#define STG_W   (6 * STG_ROW)            // 204 f4 per warp
#define SMEM_BYTES ((TAB3_F4 + WARPS * STG_W) * 16)   // 167424 B

// fp16 tables: [dim][g][64 halfs] — comps 0..47 real, 48..63 zero padding.
__device__ __half g_tH[3 * G * 64];

__global__ void cp_prep(const float* __restrict__ p0,
                        const float* __restrict__ p1,
                        const float* __restrict__ p2) {
    int idx = blockIdx.x * blockDim.x + threadIdx.x;   // over 3*300*64
    if (idx >= 3 * G * 64) return;
    int d   = idx / (G * 64);
    int rem = idx - d * (G * 64);
    int g   = rem >> 6;
    int c   = rem & 63;
    const float* p = (d == 0) ? p0 : ((d == 1) ? p1 : p2);
    float v = (c < 48) ? p[c * G + g] : 0.0f;
    g_tH[idx] = __float2half(v);
}

// Lerp 8 comps (4x half2) entirely in half2: v = a + w*(b-a).
__device__ __forceinline__ void lerp8h(float4 ra, float4 rb, __half2 w2, __half2* v) {
    const __half2* A = reinterpret_cast<const __half2*>(&ra);
    const __half2* B = reinterpret_cast<const __half2*>(&rb);
    #pragma unroll
    for (int i = 0; i < 4; i++)
        v[i] = __hfma2(w2, __hsub2(B[i], A[i]), A[i]);
}

__global__ __launch_bounds__(BLK, 1) void cp_eval(const float* __restrict__ xyz,
                                                  float* __restrict__ out,
                                                  const float4* __restrict__ gtab) {
    extern __shared__ float4 sh4[];
    for (int i = threadIdx.x; i < TAB3_F4; i += BLK) sh4[i] = gtab[i];
    __syncthreads();

    const int lane = threadIdx.x & 31;
    const int warp = threadIdx.x >> 5;
    const int l7   = lane & 7;
    float4* stg = sh4 + TAB3_F4 + warp * STG_W;
    const int gw = blockIdx.x * WARPS + warp;

    for (int tile = gw; tile < TILES; tile += NBLOCKS * WARPS) {
        const int n = tile * 32 + lane;

        float x = xyz[3 * n + 0];
        float y = xyz[3 * n + 1];
        float z = xyz[3 * n + 2];

        float px = (x + 1.0f) * 0.5f * (float)(G - 1);
        float py = (y + 1.0f) * 0.5f * (float)(G - 1);
        float pz = (z + 1.0f) * 0.5f * (float)(G - 1);

        int i0x = min(max((int)floorf(px), 0), G - 1);
        int i0y = min(max((int)floorf(py), 0), G - 1);
        int i0z = min(max((int)floorf(pz), 0), G - 1);
        int i1x = min(i0x + 1, G - 1);
        int i1y = min(i0y + 1, G - 1);
        int i1z = min(i0z + 1, G - 1);

        __half2 wx2 = __float2half2_rn(px - (float)i0x);
        __half2 wy2 = __float2half2_rn(py - (float)i0y);
        __half2 wz2 = __float2half2_rn(pz - (float)i0z);

        const float4* bx0 = sh4 + 0 * TAB_F4 + ROW_F4 * i0x;
        const float4* bx1 = sh4 + 0 * TAB_F4 + ROW_F4 * i1x;
        const float4* by0 = sh4 + 1 * TAB_F4 + ROW_F4 * i0y;
        const float4* by1 = sh4 + 1 * TAB_F4 + ROW_F4 * i1y;
        const float4* bz0 = sh4 + 2 * TAB_F4 + ROW_F4 * i0z;
        const float4* bz1 = sh4 + 2 * TAB_F4 + ROW_F4 * i1z;

        // XOR-rotation: step k, chunk c = k^l7 (bank group = c, CF).
        // Chunks 6,7 don't exist -> lanes predicated off (6 of 8 active/step).
        #pragma unroll
        for (int k = 0; k < 8; k++) {
            int c = k ^ l7;
            if (c < 6) {
                __half2 vx[4], vy[4], vz[4];
                lerp8h(bx0[c], bx1[c], wx2, vx);
                lerp8h(by0[c], by1[c], wy2, vy);
                lerp8h(bz0[c], bz1[c], wz2, vz);

                float4 fr;
                __half2* F = reinterpret_cast<__half2*>(&fr);
                #pragma unroll
                for (int i = 0; i < 4; i++)
                    F[i] = __hmul2(__hmul2(vx[i], vy[i]), vz[i]);

                // Store group (2c + lane) & 7 — lane-bijection per octet for all k.
                stg[c * STG_ROW + lane] = fr;
            }
        }
        __syncwarp();

        // Readback own point's comps (column lane), convert, coalesced STG.32.
        #pragma unroll
        for (int r = 0; r < 6; r++) {
            float4 v = stg[r * STG_ROW + lane];
            const __half2* H = reinterpret_cast<const __half2*>(&v);
            #pragma unroll
            for (int j = 0; j < 4; j++) {
                float2 f = __half22float2(H[j]);
                int c = 8 * r + 2 * j;
                out[c * NPTS + n]       = f.x;
                out[(c + 1) * NPTS + n] = f.y;
            }
        }
        __syncwarp();   // staging reused next tile
    }
}

extern "C" void kernel_launch(void* const* d_in, const int* in_sizes, int n_in,
                              void* d_out, int out_size) {
    const float* xyz = (const float*)d_in[0];
    const float* p0  = (const float*)d_in[1];
    const float* p1  = (const float*)d_in[2];
    const float* p2  = (const float*)d_in[3];
    float* out = (float*)d_out;

    cp_prep<<<(3 * G * 64 + 255) / 256, 256>>>(p0, p1, p2);

    static bool attr_set = false;
    if (!attr_set) {
        cudaFuncSetAttribute(cp_eval, cudaFuncAttributeMaxDynamicSharedMemorySize, SMEM_BYTES);
        attr_set = true;
    }

    float4* tH;
    cudaGetSymbolAddress((void**)&tH, g_tH);

    cp_eval<<<NBLOCKS, BLK, SMEM_BYTES>>>(xyz, out, tH);
}

// round 8
// speedup vs baseline: 2.9295x; 1.0477x over previous
#include <cuda_runtime.h>
#include <cuda_fp16.h>

#define NPTS    2000000
#define G       300
#define BLK     640
#define WARPS   (BLK / 32)               // 20
#define NBLOCKS 152
#define TILES   (NPTS / 32)              // 62500 (exact)

#define ROW_F4  8                        // 8 float4 = 128 B/row = 64 halfs (48 used)
#define TAB_F4  (G * ROW_F4)             // 2400 f4 per table
#define TAB3_F4 (3 * TAB_F4)             // 7200 f4 = 115200 B
#define STG_ROW 34                       // staging row stride (float4): group=(2c+lane)&7, CF
#define STG_W   (6 * STG_ROW)            // 204 f4 per warp
#define SMEM_BYTES ((TAB3_F4 + WARPS * STG_W) * 16)   // 180480 B

// fp16 tables: [dim][g][64 halfs] — comps 0..47 real, 48..63 zero padding.
__device__ __half g_tH[3 * G * 64];

__global__ void cp_prep(const float* __restrict__ p0,
                        const float* __restrict__ p1,
                        const float* __restrict__ p2) {
    int idx = blockIdx.x * blockDim.x + threadIdx.x;   // over 3*300*64
    if (idx >= 3 * G * 64) return;
    int d   = idx / (G * 64);
    int rem = idx - d * (G * 64);
    int g   = rem >> 6;
    int c   = rem & 63;
    const float* p = (d == 0) ? p0 : ((d == 1) ? p1 : p2);
    float v = (c < 48) ? p[c * G + g] : 0.0f;
    g_tH[idx] = __float2half(v);
}

// Lerp 8 comps (4x half2) entirely in half2: v = a + w*(b-a).
__device__ __forceinline__ void lerp8h(float4 ra, float4 rb, __half2 w2, __half2* v) {
    const __half2* A = reinterpret_cast<const __half2*>(&ra);
    const __half2* B = reinterpret_cast<const __half2*>(&rb);
    #pragma unroll
    for (int i = 0; i < 4; i++)
        v[i] = __hfma2(w2, __hsub2(B[i], A[i]), A[i]);
}

__global__ __launch_bounds__(BLK, 1) void cp_eval(const float* __restrict__ xyz,
                                                  float* __restrict__ out,
                                                  const float4* __restrict__ gtab) {
    extern __shared__ float4 sh4[];
    for (int i = threadIdx.x; i < TAB3_F4; i += BLK) sh4[i] = gtab[i];
    __syncthreads();

    const int lane = threadIdx.x & 31;
    const int warp = threadIdx.x >> 5;
    const int l7   = lane & 7;
    float4* stg = sh4 + TAB3_F4 + warp * STG_W;
    const int gw = blockIdx.x * WARPS + warp;

    for (int tile = gw; tile < TILES; tile += NBLOCKS * WARPS) {
        const int n = tile * 32 + lane;

        float x = xyz[3 * n + 0];
        float y = xyz[3 * n + 1];
        float z = xyz[3 * n + 2];

        float px = (x + 1.0f) * 0.5f * (float)(G - 1);
        float py = (y + 1.0f) * 0.5f * (float)(G - 1);
        float pz = (z + 1.0f) * 0.5f * (float)(G - 1);

        int i0x = min(max((int)floorf(px), 0), G - 1);
        int i0y = min(max((int)floorf(py), 0), G - 1);
        int i0z = min(max((int)floorf(pz), 0), G - 1);
        int i1x = min(i0x + 1, G - 1);
        int i1y = min(i0y + 1, G - 1);
        int i1z = min(i0z + 1, G - 1);

        __half2 wx2 = __float2half2_rn(px - (float)i0x);
        __half2 wy2 = __float2half2_rn(py - (float)i0y);
        __half2 wz2 = __float2half2_rn(pz - (float)i0z);

        const float4* bx0 = sh4 + 0 * TAB_F4 + ROW_F4 * i0x;
        const float4* bx1 = sh4 + 0 * TAB_F4 + ROW_F4 * i1x;
        const float4* by0 = sh4 + 1 * TAB_F4 + ROW_F4 * i0y;
        const float4* by1 = sh4 + 1 * TAB_F4 + ROW_F4 * i1y;
        const float4* bz0 = sh4 + 2 * TAB_F4 + ROW_F4 * i0z;
        const float4* bz1 = sh4 + 2 * TAB_F4 + ROW_F4 * i1z;

        // XOR-rotation: step k, chunk c = k^l7 (bank group = c, CF).
        // Chunks 6,7 don't exist -> lanes predicated off (6 of 8 active/step).
        #pragma unroll
        for (int k = 0; k < 8; k++) {
            int c = k ^ l7;
            if (c < 6) {
                __half2 vx[4], vy[4], vz[4];
                lerp8h(bx0[c], bx1[c], wx2, vx);
                lerp8h(by0[c], by1[c], wy2, vy);
                lerp8h(bz0[c], bz1[c], wz2, vz);

                float4 fr;
                __half2* F = reinterpret_cast<__half2*>(&fr);
                #pragma unroll
                for (int i = 0; i < 4; i++)
                    F[i] = __hmul2(__hmul2(vx[i], vy[i]), vz[i]);

                // Store group (2c + lane) & 7 — lane-bijection per octet for all k.
                stg[c * STG_ROW + lane] = fr;
            }
        }
        __syncwarp();

        // Readback own point's comps (column lane), convert, coalesced STG.32.
        #pragma unroll
        for (int r = 0; r < 6; r++) {
            float4 v = stg[r * STG_ROW + lane];
            const __half2* H = reinterpret_cast<const __half2*>(&v);
            #pragma unroll
            for (int j = 0; j < 4; j++) {
                float2 f = __half22float2(H[j]);
                int c = 8 * r + 2 * j;
                out[c * NPTS + n]       = f.x;
                out[(c + 1) * NPTS + n] = f.y;
            }
        }
        __syncwarp();   // staging reused next tile
    }
}

extern "C" void kernel_launch(void* const* d_in, const int* in_sizes, int n_in,
                              void* d_out, int out_size) {
    const float* xyz = (const float*)d_in[0];
    const float* p0  = (const float*)d_in[1];
    const float* p1  = (const float*)d_in[2];
    const float* p2  = (const float*)d_in[3];
    float* out = (float*)d_out;

    cp_prep<<<(3 * G * 64 + 255) / 256, 256>>>(p0, p1, p2);

    static bool attr_set = false;
    if (!attr_set) {
        cudaFuncSetAttribute(cp_eval, cudaFuncAttributeMaxDynamicSharedMemorySize, SMEM_BYTES);
        attr_set = true;
    }

    float4* tH;
    cudaGetSymbolAddress((void**)&tH, g_tH);

    cp_eval<<<NBLOCKS, BLK, SMEM_BYTES>>>(xyz, out, tH);
}

// round 9
// speedup vs baseline: 2.9384x; 1.0030x over previous
#include <cuda_runtime.h>
#include <cuda_fp16.h>

#define NPTS    2000000
#define G       300
#define BLK     768
#define WARPS   (BLK / 32)               // 24
#define NBLOCKS 152
#define TILES   (NPTS / 32)              // 62500 (exact)

#define ROW_F4  8                        // 8 float4 = 128 B/row = 64 halfs (48 used)
#define TAB_F4  (G * ROW_F4)             // 2400 f4 per table
#define TAB3_F4 (3 * TAB_F4)             // 7200 f4 = 115200 B
#define STG_ROW 34                       // staging row stride (float4): group=(2c+lane)&7, CF
#define STG_W   (6 * STG_ROW)            // 204 f4 per warp
#define SMEM_BYTES ((TAB3_F4 + WARPS * STG_W) * 16)   // 193536 B

// fp16 tables: [dim][g][64 halfs] — comps 0..47 real, 48..63 zero padding.
__device__ __half g_tH[3 * G * 64];

// Prep: 4 elems/thread, coalesced writes. 3*G*64/4 = 14400 threads.
__global__ void cp_prep(const float* __restrict__ p0,
                        const float* __restrict__ p1,
                        const float* __restrict__ p2) {
    int t = blockIdx.x * blockDim.x + threadIdx.x;     // over 3*300*16 quads
    if (t >= 3 * G * 16) return;
    int base = t * 4;
    int d    = base / (G * 64);
    int rem  = base - d * (G * 64);
    int g    = rem >> 6;
    int c    = rem & 63;
    const float* p = (d == 0) ? p0 : ((d == 1) ? p1 : p2);
    __half h[4];
    #pragma unroll
    for (int i = 0; i < 4; i++) {
        int ci = c + i;
        float v = (ci < 48) ? __ldg(p + ci * G + g) : 0.0f;
        h[i] = __float2half(v);
    }
    *reinterpret_cast<uint2*>(g_tH + base) = *reinterpret_cast<uint2*>(h);
}

// Lerp 8 comps (4x half2) entirely in half2: v = a + w*(b-a).
__device__ __forceinline__ void lerp8h(float4 ra, float4 rb, __half2 w2, __half2* v) {
    const __half2* A = reinterpret_cast<const __half2*>(&ra);
    const __half2* B = reinterpret_cast<const __half2*>(&rb);
    #pragma unroll
    for (int i = 0; i < 4; i++)
        v[i] = __hfma2(w2, __hsub2(B[i], A[i]), A[i]);
}

__global__ __launch_bounds__(BLK, 1) void cp_eval(const float* __restrict__ xyz,
                                                  float* __restrict__ out,
                                                  const float4* __restrict__ gtab) {
    extern __shared__ float4 sh4[];
    for (int i = threadIdx.x; i < TAB3_F4; i += BLK) sh4[i] = gtab[i];
    __syncthreads();

    const int lane = threadIdx.x & 31;
    const int warp = threadIdx.x >> 5;
    const int l7   = lane & 7;
    float4* stg = sh4 + TAB3_F4 + warp * STG_W;
    const int gw   = blockIdx.x * WARPS + warp;
    const int step = NBLOCKS * WARPS;

    // Prefetch first tile's coords.
    float x, y, z;
    {
        int n = gw * 32 + lane;
        x = __ldg(xyz + 3 * n + 0);
        y = __ldg(xyz + 3 * n + 1);
        z = __ldg(xyz + 3 * n + 2);
    }

    for (int tile = gw; tile < TILES; tile += step) {
        const int n = tile * 32 + lane;

        // Index/weight math from the (already resident) prefetched coords.
        float px = (x + 1.0f) * 0.5f * (float)(G - 1);
        float py = (y + 1.0f) * 0.5f * (float)(G - 1);
        float pz = (z + 1.0f) * 0.5f * (float)(G - 1);

        int i0x = min(max((int)floorf(px), 0), G - 1);
        int i0y = min(max((int)floorf(py), 0), G - 1);
        int i0z = min(max((int)floorf(pz), 0), G - 1);
        int i1x = min(i0x + 1, G - 1);
        int i1y = min(i0y + 1, G - 1);
        int i1z = min(i0z + 1, G - 1);

        __half2 wx2 = __float2half2_rn(px - (float)i0x);
        __half2 wy2 = __float2half2_rn(py - (float)i0y);
        __half2 wz2 = __float2half2_rn(pz - (float)i0z);

        const float4* bx0 = sh4 + 0 * TAB_F4 + ROW_F4 * i0x;
        const float4* bx1 = sh4 + 0 * TAB_F4 + ROW_F4 * i1x;
        const float4* by0 = sh4 + 1 * TAB_F4 + ROW_F4 * i0y;
        const float4* by1 = sh4 + 1 * TAB_F4 + ROW_F4 * i1y;
        const float4* bz0 = sh4 + 2 * TAB_F4 + ROW_F4 * i0z;
        const float4* bz1 = sh4 + 2 * TAB_F4 + ROW_F4 * i1z;

        // Prefetch NEXT tile's coords; latency overlaps the LDS storm below.
        int tn = tile + step;
        if (tn < TILES) {
            int nn = tn * 32 + lane;
            x = __ldg(xyz + 3 * nn + 0);
            y = __ldg(xyz + 3 * nn + 1);
            z = __ldg(xyz + 3 * nn + 2);
        }

        // XOR-rotation: step k, chunk c = k^l7 (bank group = c, CF).
        // Chunks 6,7 don't exist -> lanes predicated off (6 of 8 active/step).
        #pragma unroll
        for (int k = 0; k < 8; k++) {
            int c = k ^ l7;
            if (c < 6) {
                __half2 vx[4], vy[4], vz[4];
                lerp8h(bx0[c], bx1[c], wx2, vx);
                lerp8h(by0[c], by1[c], wy2, vy);
                lerp8h(bz0[c], bz1[c], wz2, vz);

                float4 fr;
                __half2* F = reinterpret_cast<__half2*>(&fr);
                #pragma unroll
                for (int i = 0; i < 4; i++)
                    F[i] = __hmul2(__hmul2(vx[i], vy[i]), vz[i]);

                // Store group (2c + lane) & 7 — lane-bijection per octet for all k.
                stg[c * STG_ROW + lane] = fr;
            }
        }
        __syncwarp();

        // Readback own point's comps (column lane), convert, coalesced STG.32.
        #pragma unroll
        for (int r = 0; r < 6; r++) {
            float4 v = stg[r * STG_ROW + lane];
            const __half2* H = reinterpret_cast<const __half2*>(&v);
            #pragma unroll
            for (int j = 0; j < 4; j++) {
                float2 f = __half22float2(H[j]);
                int c = 8 * r + 2 * j;
                out[c * NPTS + n]       = f.x;
                out[(c + 1) * NPTS + n] = f.y;
            }
        }
        __syncwarp();   // staging reused next tile
    }
}

extern "C" void kernel_launch(void* const* d_in, const int* in_sizes, int n_in,
                              void* d_out, int out_size) {
    const float* xyz = (const float*)d_in[0];
    const float* p0  = (const float*)d_in[1];
    const float* p1  = (const float*)d_in[2];
    const float* p2  = (const float*)d_in[3];
    float* out = (float*)d_out;

    cp_prep<<<(3 * G * 16 + 255) / 256, 256>>>(p0, p1, p2);

    static bool attr_set = false;
    if (!attr_set) {
        cudaFuncSetAttribute(cp_eval, cudaFuncAttributeMaxDynamicSharedMemorySize, SMEM_BYTES);
        attr_set = true;
    }

    float4* tH;
    cudaGetSymbolAddress((void**)&tH, g_tH);

    cp_eval<<<NBLOCKS, BLK, SMEM_BYTES>>>(xyz, out, tH);
}